// round 7
// baseline (speedup 1.0000x reference)
#include <cuda_runtime.h>
#include <cstdint>
#include <cstddef>

#define D_MODEL 1024
#define NH      16
#define DH      64
#define BB      4
#define TT      2048
#define BT      (BB * TT)

__device__ float g_qkv[(size_t)BT * 3 * D_MODEL];   // [B*T, 3072]
__device__ float g_y  [(size_t)BT * D_MODEL];       // [B*T, 1024]

// ---------------------------------------------------------------------------
__device__ __forceinline__ uint32_t f2tf(float x) {
    uint32_t u;
    asm("cvt.rna.tf32.f32 %0, %1;" : "=r"(u) : "f"(x));
    return u;
}

__device__ __forceinline__ uint32_t tf_of_raw(uint32_t raw) {
    return f2tf(__uint_as_float(raw));
}

__device__ __forceinline__ void mma_tf32(float c[4], const uint32_t a[4],
                                         const uint32_t b[2]) {
    asm volatile(
        "mma.sync.aligned.m16n8k8.row.col.f32.tf32.tf32.f32 "
        "{%0,%1,%2,%3},{%4,%5,%6,%7},{%8,%9},{%0,%1,%2,%3};"
        : "+f"(c[0]), "+f"(c[1]), "+f"(c[2]), "+f"(c[3])
        : "r"(a[0]), "r"(a[1]), "r"(a[2]), "r"(a[3]), "r"(b[0]), "r"(b[1]));
}

__device__ __forceinline__ uint32_t smem_u32(const void* p) {
    uint32_t a;
    asm("{ .reg .u64 t; cvta.to.shared.u64 t, %1; cvt.u32.u64 %0, t; }"
        : "=r"(a) : "l"(p));
    return a;
}

__device__ __forceinline__ void cpa16(uint32_t dst, const void* src) {
    asm volatile("cp.async.cg.shared.global [%0], [%1], 16;"
                 :: "r"(dst), "l"(src) : "memory");
}

// ---------------------------------------------------------------------------
// TF32 GEMM v6: C[M,N] = A[M,K] * B[N,K]^T.
// Round-5 tiling (128x128, 8 warps, warp 64x32, K-chunk 32) with cp.async
// double-buffered staging (raw fp32 in smem; cvt to tf32 at fragment load).
//   As: [mtile 8][kstep 4][aidx 4][pos 32]   pos = (4*(row&7)) ^ 4q (+j)
//   Bs: [ntile 16][kstep 4][plane 2][pos 32]
// ---------------------------------------------------------------------------
#define GEMM_SMEM (2 * 8192 * 4)   // 2 buffers x (As 4096 + Bs 4096) u32

__global__ __launch_bounds__(256, 2)
void gemm_tf32(const float* __restrict__ A, const float* __restrict__ Bw,
               float* __restrict__ C, int M, int N, int K) {
    extern __shared__ __align__(16) uint32_t sm[];   // [2][8192]

    const int tid    = threadIdx.x;
    const int lane   = tid & 31;
    const int wid    = tid >> 5;
    const int warp_m = wid >> 2;
    const int warp_n = wid & 3;
    const int m0     = blockIdx.y * 128;
    const int n0     = blockIdx.x * 128;

    const uint32_t smaddr = smem_u32(sm);

    // per-thread staging coords (4 A-rows + 4 B-rows, 8 lanes per 128B row)
    // it-th element: lin = tid + it*256, row = lin>>3, q = lin&7
    float acc[4][4][4];
    #pragma unroll
    for (int i = 0; i < 4; i++)
        #pragma unroll
        for (int j = 0; j < 4; j++)
            #pragma unroll
            for (int r = 0; r < 4; r++) acc[i][j][r] = 0.f;

    const int NCH = K / 32;

    // ---- stage chunk 0 ----
    {
        #pragma unroll
        for (int it = 0; it < 4; it++) {
            int lin = tid + it * 256;
            int row = lin >> 3, q = lin & 7;
            int offA = ((((row >> 4) * 4 + (q >> 1)) * 4 + (((row >> 3) & 1) + 2 * (q & 1))) << 5)
                       + ((((row & 7) << 2)) ^ (q << 2));
            cpa16(smaddr + offA * 4, &A[(size_t)(m0 + row) * K + q * 4]);
            int offB = 4096 + ((((row >> 3) * 4 + (q >> 1)) * 2 + (q & 1)) << 5)
                       + ((((row & 7) << 2)) ^ (q << 2));
            cpa16(smaddr + offB * 4, &Bw[(size_t)(n0 + row) * K + q * 4]);
        }
        asm volatile("cp.async.commit_group;" ::: "memory");
    }

    for (int c = 0; c < NCH; c++) {
        const int cur = (c & 1) * 8192;
        if (c + 1 < NCH) {
            const int nb = ((c + 1) & 1) * 8192;
            const int k0 = (c + 1) * 32;
            #pragma unroll
            for (int it = 0; it < 4; it++) {
                int lin = tid + it * 256;
                int row = lin >> 3, q = lin & 7;
                int offA = ((((row >> 4) * 4 + (q >> 1)) * 4 + (((row >> 3) & 1) + 2 * (q & 1))) << 5)
                           + ((((row & 7) << 2)) ^ (q << 2));
                cpa16(smaddr + (nb + offA) * 4, &A[(size_t)(m0 + row) * K + k0 + q * 4]);
                int offB = 4096 + ((((row >> 3) * 4 + (q >> 1)) * 2 + (q & 1)) << 5)
                           + ((((row & 7) << 2)) ^ (q << 2));
                cpa16(smaddr + (nb + offB) * 4, &Bw[(size_t)(n0 + row) * K + k0 + q * 4]);
            }
            asm volatile("cp.async.commit_group;" ::: "memory");
            asm volatile("cp.async.wait_group 1;" ::: "memory");
        } else {
            asm volatile("cp.async.wait_group 0;" ::: "memory");
        }
        __syncthreads();

        const uint32_t* As = sm + cur;
        const uint32_t* Bs = sm + cur + 4096;
        #pragma unroll
        for (int ks = 0; ks < 4; ks++) {
            uint32_t af[4][4], bf[4][2];
            #pragma unroll
            for (int i = 0; i < 4; i++) {
                int base = ((warp_m * 4 + i) * 4 + ks) * 4 * 32;
                #pragma unroll
                for (int aidx = 0; aidx < 4; aidx++) {
                    int q = 2 * ks + (aidx >> 1);
                    af[i][aidx] = tf_of_raw(As[base + aidx * 32 + (lane ^ (q << 2))]);
                }
            }
            #pragma unroll
            for (int j = 0; j < 4; j++) {
                int base = ((warp_n * 4 + j) * 4 + ks) * 2 * 32;
                #pragma unroll
                for (int p = 0; p < 2; p++) {
                    int q = 2 * ks + p;
                    bf[j][p] = tf_of_raw(Bs[base + p * 32 + (lane ^ (q << 2))]);
                }
            }
            #pragma unroll
            for (int i = 0; i < 4; i++)
                #pragma unroll
                for (int j = 0; j < 4; j++)
                    mma_tf32(acc[i][j], af[i], bf[j]);
        }
        __syncthreads();
    }

    const int g = lane >> 2, t = lane & 3;
    #pragma unroll
    for (int i = 0; i < 4; i++) {
        int rbase = m0 + warp_m * 64 + i * 16 + g;
        #pragma unroll
        for (int j = 0; j < 4; j++) {
            int cbase = n0 + warp_n * 32 + j * 8 + t * 2;
            *(float2*)&C[(size_t)rbase * N + cbase] =
                make_float2(acc[i][j][0], acc[i][j][1]);
            *(float2*)&C[(size_t)(rbase + 8) * N + cbase] =
                make_float2(acc[i][j][2], acc[i][j][3]);
        }
    }
}

// ---------------------------------------------------------------------------
// Tensor-core flash attention (tf32, mma.sync) — round-5 known-good version.
// ---------------------------------------------------------------------------
__global__ __launch_bounds__(128)
void attn_tc() {
    __shared__ __align__(16) uint32_t Kf[8 * 8 * 2 * 32];
    __shared__ __align__(16) uint32_t Vf[8 * 8 * 2 * 32];

    const int tid  = threadIdx.x;
    const int lane = tid & 31;
    const int w    = tid >> 5;
    const int g    = lane >> 2;
    const int t    = lane & 3;
    const int qt   = blockIdx.x;
    const int h    = blockIdx.y;
    const int b    = blockIdx.z;

    const size_t base = (size_t)b * TT * (3 * D_MODEL);
    const int    hcol = h * DH;
    const int    q0   = qt * 64 + w * 16;

    uint32_t qf[8][4];
    {
        const float* qA = g_qkv + base + (size_t)(q0 + g) * (3 * D_MODEL) + hcol;
        const float* qB = qA + (size_t)8 * (3 * D_MODEL);
        #pragma unroll
        for (int kg = 0; kg < 8; kg++) {
            qf[kg][0] = f2tf(qA[kg * 8 + t]);
            qf[kg][1] = f2tf(qB[kg * 8 + t]);
            qf[kg][2] = f2tf(qA[kg * 8 + t + 4]);
            qf[kg][3] = f2tf(qB[kg * 8 + t + 4]);
        }
    }

    float m0v = -1e30f, m1v = -1e30f, l0 = 0.f, l1 = 0.f;
    float o[8][4];
    #pragma unroll
    for (int nt = 0; nt < 8; nt++)
        #pragma unroll
        for (int e = 0; e < 4; e++) o[nt][e] = 0.f;

    const int src  = (lane & ~3) | (t >> 1);
    const int src2 = src + 2;

    for (int j = 0; j <= qt; j++) {
        __syncthreads();
        #pragma unroll
        for (int it = 0; it < 8; it++) {
            int lin = tid + it * 128;
            int key = (lin & 7) | ((lin >> 7) << 3);
            int c   = (lin >> 3) & 15;
            const float* kvp = g_qkv + base + (size_t)(j * 64 + key) * (3 * D_MODEL)
                               + D_MODEL + hcol + c * 4;
            float4 kv4 = *(const float4*)kvp;
            float4 vv4 = *(const float4*)(kvp + D_MODEL);

            int koff = (((((c >> 1) * 8 + (key >> 3)) * 2) + (c & 1)) << 5) + ((key & 7) << 2);
            *(uint4*)&Kf[koff] = make_uint4(f2tf(kv4.x), f2tf(kv4.y), f2tf(kv4.z), f2tf(kv4.w));

            int kgv  = key >> 3;
            int pv   = (key >> 2) & 1;
            int ntv  = c >> 1;
            int vb   = ((kgv * 8 + ntv) * 2 + pv) << 5;
            int lb   = 16 * (c & 1) + (key & 3);
            int swz  = (4 * (ntv & 1)) ^ (8 * pv);
            float ve[4] = {vv4.x, vv4.y, vv4.z, vv4.w};
            #pragma unroll
            for (int jj = 0; jj < 4; jj++)
                Vf[vb + ((lb + 4 * jj) ^ swz)] = f2tf(ve[jj]);
        }
        __syncthreads();

        const int lim = (j == qt) ? (2 * w + 2) : 8;

        float s[8][4];
        #pragma unroll
        for (int nt = 0; nt < 8; nt++) {
            if (nt < lim) {
                #pragma unroll
                for (int e = 0; e < 4; e++) s[nt][e] = 0.f;
                #pragma unroll
                for (int kg = 0; kg < 8; kg++) {
                    int kb = ((kg * 8 + nt) * 2) << 5;
                    uint32_t bf[2] = {Kf[kb + lane], Kf[kb + 32 + lane]};
                    mma_tf32(s[nt], qf[kg], bf);
                }
            }
        }

        #pragma unroll
        for (int nt = 0; nt < 8; nt++) {
            if (nt < lim) {
                #pragma unroll
                for (int e = 0; e < 4; e++) {
                    float v = s[nt][e] * 0.125f;
                    if (j == qt) {
                        int keyl = nt * 8 + 2 * t + (e & 1);
                        int rowl = w * 16 + g + ((e >> 1) << 3);
                        if (keyl > rowl) v = -1e30f;
                    }
                    s[nt][e] = v;
                }
            }
        }

        float rm0 = -1e30f, rm1 = -1e30f;
        #pragma unroll
        for (int nt = 0; nt < 8; nt++) {
            if (nt < lim) {
                rm0 = fmaxf(rm0, fmaxf(s[nt][0], s[nt][1]));
                rm1 = fmaxf(rm1, fmaxf(s[nt][2], s[nt][3]));
            }
        }
        rm0 = fmaxf(rm0, __shfl_xor_sync(0xffffffffu, rm0, 1));
        rm0 = fmaxf(rm0, __shfl_xor_sync(0xffffffffu, rm0, 2));
        rm1 = fmaxf(rm1, __shfl_xor_sync(0xffffffffu, rm1, 1));
        rm1 = fmaxf(rm1, __shfl_xor_sync(0xffffffffu, rm1, 2));

        float mn0 = fmaxf(m0v, rm0), mn1 = fmaxf(m1v, rm1);
        float a0 = __expf(m0v - mn0), a1 = __expf(m1v - mn1);
        m0v = mn0; m1v = mn1;

        float rs0 = 0.f, rs1 = 0.f;
        #pragma unroll
        for (int nt = 0; nt < 8; nt++) {
            if (nt < lim) {
                s[nt][0] = __expf(s[nt][0] - mn0);
                s[nt][1] = __expf(s[nt][1] - mn0);
                s[nt][2] = __expf(s[nt][2] - mn1);
                s[nt][3] = __expf(s[nt][3] - mn1);
                rs0 += s[nt][0] + s[nt][1];
                rs1 += s[nt][2] + s[nt][3];
            }
        }
        rs0 += __shfl_xor_sync(0xffffffffu, rs0, 1);
        rs0 += __shfl_xor_sync(0xffffffffu, rs0, 2);
        rs1 += __shfl_xor_sync(0xffffffffu, rs1, 1);
        rs1 += __shfl_xor_sync(0xffffffffu, rs1, 2);
        l0 = l0 * a0 + rs0;
        l1 = l1 * a1 + rs1;

        #pragma unroll
        for (int nt = 0; nt < 8; nt++) {
            o[nt][0] *= a0; o[nt][1] *= a0;
            o[nt][2] *= a1; o[nt][3] *= a1;
        }

        uint32_t p[8][4];
        #pragma unroll
        for (int kg = 0; kg < 8; kg++) {
            if (kg < lim) {
                uint32_t c0 = f2tf(s[kg][0]), c1 = f2tf(s[kg][1]);
                uint32_t c2 = f2tf(s[kg][2]), c3 = f2tf(s[kg][3]);
                uint32_t u0 = __shfl_sync(0xffffffffu, c0, src);
                uint32_t u1 = __shfl_sync(0xffffffffu, c1, src);
                uint32_t u2 = __shfl_sync(0xffffffffu, c2, src);
                uint32_t u3 = __shfl_sync(0xffffffffu, c3, src);
                uint32_t v0 = __shfl_sync(0xffffffffu, c0, src2);
                uint32_t v1 = __shfl_sync(0xffffffffu, c1, src2);
                uint32_t v2 = __shfl_sync(0xffffffffu, c2, src2);
                uint32_t v3 = __shfl_sync(0xffffffffu, c3, src2);
                bool odd = (t & 1);
                p[kg][0] = odd ? u1 : u0;
                p[kg][1] = odd ? u3 : u2;
                p[kg][2] = odd ? v1 : v0;
                p[kg][3] = odd ? v3 : v2;
            }
        }

        #pragma unroll
        for (int nt = 0; nt < 8; nt++) {
            int sw0 = 4 * (nt & 1);
            #pragma unroll
            for (int kg = 0; kg < 8; kg++) {
                if (kg < lim) {
                    int vb = ((kg * 8 + nt) * 2) << 5;
                    uint32_t bf[2] = {Vf[vb + (lane ^ sw0)],
                                      Vf[vb + 32 + (lane ^ sw0 ^ 8)]};
                    mma_tf32(o[nt], p[kg], bf);
                }
            }
        }
    }

    float inv0 = 1.f / l0, inv1 = 1.f / l1;
    size_t r0 = (size_t)(b * TT + q0 + g) * D_MODEL + hcol;
    size_t r1 = (size_t)(b * TT + q0 + g + 8) * D_MODEL + hcol;
    #pragma unroll
    for (int nt = 0; nt < 8; nt++) {
        int cb = nt * 8 + 2 * t;
        *(float2*)&g_y[r0 + cb] = make_float2(o[nt][0] * inv0, o[nt][1] * inv0);
        *(float2*)&g_y[r1 + cb] = make_float2(o[nt][2] * inv1, o[nt][3] * inv1);
    }
}

// ---------------------------------------------------------------------------
extern "C" void kernel_launch(void* const* d_in, const int* in_sizes, int n_in,
                              void* d_out, int out_size) {
    const float* x      = (const float*)d_in[0];
    const float* w_qkv  = (const float*)d_in[1];
    const float* w_proj = (const float*)d_in[2];
    float*       out    = (float*)d_out;

    float *qkv_ptr = nullptr, *y_ptr = nullptr;
    cudaGetSymbolAddress((void**)&qkv_ptr, g_qkv);
    cudaGetSymbolAddress((void**)&y_ptr,   g_y);

    cudaFuncSetAttribute(gemm_tf32, cudaFuncAttributeMaxDynamicSharedMemorySize, GEMM_SMEM);

    gemm_tf32<<<dim3(3 * D_MODEL / 128, BT / 128), 256, GEMM_SMEM>>>(
        x, w_qkv, qkv_ptr, BT, 3 * D_MODEL, D_MODEL);

    attn_tc<<<dim3(TT / 64, NH, BB), 128>>>();

    gemm_tf32<<<dim3(D_MODEL / 128, BT / 128), 256, GEMM_SMEM>>>(
        y_ptr, w_proj, out, BT, D_MODEL, D_MODEL);
}